// round 8
// baseline (speedup 1.0000x reference)
#include <cuda_runtime.h>
#include <cuda_bf16.h>
#include <cstdint>

// Fixed problem shape: N=50000, IN_CH=256, OUT_CH=128, NNZ=800000 per matrix.
#define NNODES 50000
#define FEAT   128
#define MAXNNZ 800000
#define TOT    (NNODES * FEAT)
#define SLOTS  64                  // per-row bucket capacity (Poisson(16): P(>64) ~ 1e-22)
#define FULLM  0xFFFFFFFFu

// ---------------------------------------------------------------------------
// Static device scratch. m=0 features, m=1 phi_inv, m=2 phi.
// ---------------------------------------------------------------------------
__device__ float g_buf0[TOT];                         // filtered  [N,128]
__device__ float g_buf1[TOT];                         // tmp       [N,128]
__device__ int   g_cursor[3 * NNODES];                // per-row fill cursors == counts
__device__ int2  g_slots[3 * NNODES * SLOTS];         // (col, val-bits) buckets

// ---------------------------------------------------------------------------
// Zero the cursors (600 KB).
// ---------------------------------------------------------------------------
__global__ void zero_cursor_kernel() {
    int i = blockIdx.x * blockDim.x + threadIdx.x;
    if (i < 3 * NNODES) g_cursor[i] = 0;
}

// ---------------------------------------------------------------------------
// Fused bucket-scatter for all three matrices. blockIdx.y selects the matrix.
// 4 nnz per thread for ILP. theta (matrix 2) folds phi @ diag(theta) in.
// All index math 32-bit (buffers < 2^31 elements).
// ---------------------------------------------------------------------------
__global__ void scatter_kernel(const int*   __restrict__ rows0, const float* __restrict__ vals0, int nnz0,
                               const int*   __restrict__ rows1, const float* __restrict__ vals1, int nnz1,
                               const int*   __restrict__ rows2, const float* __restrict__ vals2, int nnz2,
                               const float* __restrict__ theta) {
    const int m = blockIdx.y;
    const int* rows; const int* cols; const float* vals; int nnz;
    const float* th = nullptr;
    if (m == 0)      { rows = rows0; cols = rows0 + nnz0; vals = vals0; nnz = nnz0; }
    else if (m == 1) { rows = rows1; cols = rows1 + nnz1; vals = vals1; nnz = nnz1; }
    else             { rows = rows2; cols = rows2 + nnz2; vals = vals2; nnz = nnz2; th = theta; }

    int base = (blockIdx.x * blockDim.x + threadIdx.x) * 4;
    if (base >= nnz) return;

    int*  cur   = g_cursor + m * NNODES;
    int2* slots = g_slots + (unsigned)m * (unsigned)(NNODES * SLOTS);

    if (base + 4 <= nnz) {
        int4   r4 = *reinterpret_cast<const int4*>(rows + base);
        int4   c4 = *reinterpret_cast<const int4*>(cols + base);
        float4 v4 = *reinterpret_cast<const float4*>(vals + base);
        int   r[4] = {r4.x, r4.y, r4.z, r4.w};
        int   c[4] = {c4.x, c4.y, c4.z, c4.w};
        float v[4] = {v4.x, v4.y, v4.z, v4.w};
        #pragma unroll
        for (int k = 0; k < 4; k++) {
            float vv = v[k];
            if (th) vv *= __ldg(th + c[k]);
            int pos = atomicAdd(cur + r[k], 1);
            slots[(unsigned)r[k] * SLOTS + (unsigned)pos] = make_int2(c[k], __float_as_int(vv));
        }
    } else {
        for (int i = base; i < nnz && i < base + 4; i++) {
            int r = __ldg(rows + i);
            int c = __ldg(cols + i);
            float vv = __ldg(vals + i);
            if (th) vv *= __ldg(th + c);
            int pos = atomicAdd(cur + r, 1);
            slots[(unsigned)r * SLOTS + (unsigned)pos] = make_int2(c, __float_as_int(vv));
        }
    }
}

// ---------------------------------------------------------------------------
// Gather SpMM: out[row,:] = sum_j val_j * dense[col_j, :]   (F = 128)
// One warp per row. Lane i prefetches entry i (one coalesced 8B load per
// warp); cols/vals broadcast via shfl. 4 independent float4 loads in flight
// per batch. __launch_bounds__(256,7) caps regs at 36 -> 87.5% occupancy:
// the binding resource is warps feeding the per-SM L1tex wavefront queue.
// 32-bit index math throughout. ReLU optionally fused.
// ---------------------------------------------------------------------------
template <bool RELU>
__global__ void __launch_bounds__(256, 7)
spmm_gather_kernel(int m,
                   const float* __restrict__ dense,
                   float*       __restrict__ out) {
    int row  = (blockIdx.x * blockDim.x + threadIdx.x) >> 5;
    int lane = threadIdx.x & 31;
    if (row >= NNODES) return;

    int cnt = __ldg(g_cursor + m * NNODES + row);
    if (cnt > SLOTS) cnt = SLOTS;
    const int2* e = g_slots + (unsigned)m * (unsigned)(NNODES * SLOTS)
                           + (unsigned)row * SLOTS;

    // One coalesced load covers entries 0..31 for the whole warp.
    int2 my_e = make_int2(0, 0);
    if (lane < cnt) my_e = __ldg(e + lane);

    float4 acc0 = make_float4(0.f, 0.f, 0.f, 0.f);
    float4 acc1 = make_float4(0.f, 0.f, 0.f, 0.f);

    const int n32 = (cnt < 32) ? cnt : 32;
    int i = 0;
    for (; i + 4 <= n32; i += 4) {
        unsigned c0 = (unsigned)__shfl_sync(FULLM, my_e.x, i);
        unsigned c1 = (unsigned)__shfl_sync(FULLM, my_e.x, i + 1);
        unsigned c2 = (unsigned)__shfl_sync(FULLM, my_e.x, i + 2);
        unsigned c3 = (unsigned)__shfl_sync(FULLM, my_e.x, i + 3);
        float v0 = __int_as_float(__shfl_sync(FULLM, my_e.y, i));
        float v1 = __int_as_float(__shfl_sync(FULLM, my_e.y, i + 1));
        float v2 = __int_as_float(__shfl_sync(FULLM, my_e.y, i + 2));
        float v3 = __int_as_float(__shfl_sync(FULLM, my_e.y, i + 3));
        // 4 independent loads in flight
        float4 x0 = __ldg(reinterpret_cast<const float4*>(dense + c0 * FEAT) + lane);
        float4 x1 = __ldg(reinterpret_cast<const float4*>(dense + c1 * FEAT) + lane);
        float4 x2 = __ldg(reinterpret_cast<const float4*>(dense + c2 * FEAT) + lane);
        float4 x3 = __ldg(reinterpret_cast<const float4*>(dense + c3 * FEAT) + lane);
        acc0.x += v0 * x0.x; acc0.y += v0 * x0.y; acc0.z += v0 * x0.z; acc0.w += v0 * x0.w;
        acc1.x += v1 * x1.x; acc1.y += v1 * x1.y; acc1.z += v1 * x1.z; acc1.w += v1 * x1.w;
        acc0.x += v2 * x2.x; acc0.y += v2 * x2.y; acc0.z += v2 * x2.z; acc0.w += v2 * x2.w;
        acc1.x += v3 * x3.x; acc1.y += v3 * x3.y; acc1.z += v3 * x3.z; acc1.w += v3 * x3.w;
    }
    for (; i < n32; i++) {
        unsigned c0 = (unsigned)__shfl_sync(FULLM, my_e.x, i);
        float    v0 = __int_as_float(__shfl_sync(FULLM, my_e.y, i));
        float4 x0 = __ldg(reinterpret_cast<const float4*>(dense + c0 * FEAT) + lane);
        acc0.x += v0 * x0.x; acc0.y += v0 * x0.y; acc0.z += v0 * x0.z; acc0.w += v0 * x0.w;
    }
    // Rare tail: rows with more than 32 entries (~1e-4 of rows).
    for (; i < cnt; i++) {
        int2 ee = __ldg(e + i);
        float vv = __int_as_float(ee.y);
        float4 x0 = __ldg(reinterpret_cast<const float4*>(dense + (unsigned)ee.x * FEAT) + lane);
        acc0.x += vv * x0.x; acc0.y += vv * x0.y; acc0.z += vv * x0.z; acc0.w += vv * x0.w;
    }

    float4 r;
    r.x = acc0.x + acc1.x;
    r.y = acc0.y + acc1.y;
    r.z = acc0.z + acc1.z;
    r.w = acc0.w + acc1.w;
    if (RELU) {
        r.x = fmaxf(r.x, 0.f); r.y = fmaxf(r.y, 0.f);
        r.z = fmaxf(r.z, 0.f); r.w = fmaxf(r.w, 0.f);
    }
    reinterpret_cast<float4*>(out + (unsigned)row * FEAT)[lane] = r;
}

// ---------------------------------------------------------------------------
// Launch sequence (graph-capturable).
// Inputs:
//   0 phi_indices int32[2,NNZ]  1 phi_values f32[NNZ]
//   2 phi_inv_indices           3 phi_inv_values
//   4 feature_indices           5 feature_values
//   6 weight_matrix f32[256,128] 7 theta f32[N]  8 dropout (ignored)
// ---------------------------------------------------------------------------
extern "C" void kernel_launch(void* const* d_in, const int* in_sizes, int n_in,
                              void* d_out, int out_size) {
    const int*   phi_idx    = (const int*)  d_in[0];
    const float* phi_vals   = (const float*)d_in[1];
    const int*   phinv_idx  = (const int*)  d_in[2];
    const float* phinv_vals = (const float*)d_in[3];
    const int*   feat_idx   = (const int*)  d_in[4];
    const float* feat_vals  = (const float*)d_in[5];
    const float* W          = (const float*)d_in[6];
    const float* theta      = (const float*)d_in[7];
    float*       out        = (float*)d_out;

    const int nnz_phi   = in_sizes[1];
    const int nnz_phinv = in_sizes[3];
    const int nnz_feat  = in_sizes[5];

    float* buf0 = nullptr; float* buf1 = nullptr;
    cudaGetSymbolAddress((void**)&buf0, g_buf0);
    cudaGetSymbolAddress((void**)&buf1, g_buf1);

    const int B = 256;

    // 1) zero per-row cursors
    zero_cursor_kernel<<<(3 * NNODES + B - 1) / B, B>>>();

    // 2) fused bucket scatter for all three matrices
    int nnz_max = nnz_feat;
    if (nnz_phinv > nnz_max) nnz_max = nnz_phinv;
    if (nnz_phi   > nnz_max) nnz_max = nnz_phi;
    dim3 sgrid((nnz_max + 4 * B - 1) / (4 * B), 3);
    scatter_kernel<<<sgrid, B>>>(feat_idx,  feat_vals,  nnz_feat,
                                 phinv_idx, phinv_vals, nnz_phinv,
                                 phi_idx,   phi_vals,   nnz_phi,
                                 theta);

    // 3) three gather SpMMs; ReLU fused into the last
    const int SG = (NNODES * 32 + B - 1) / B;    // warp per row
    spmm_gather_kernel<false><<<SG, B>>>(0, W,    buf0);
    spmm_gather_kernel<false><<<SG, B>>>(1, buf0, buf1);
    spmm_gather_kernel<true ><<<SG, B>>>(2, buf1, out);
}

// round 9
// speedup vs baseline: 1.2548x; 1.2548x over previous
#include <cuda_runtime.h>
#include <cuda_fp16.h>
#include <cstdint>

// Fixed problem shape: N=50000, IN_CH=256, OUT_CH=128, NNZ=800000 per matrix.
#define NNODES 50000
#define FEAT   128
#define MAXNNZ 800000
#define TOT    (NNODES * FEAT)
#define SLOTS  64                  // per-row bucket capacity (Poisson(16): P(>64) ~ 1e-22)
#define FULLM  0xFFFFFFFFu

// ---------------------------------------------------------------------------
// Static device scratch. m=0 features, m=1 phi_inv, m=2 phi.
// Intermediates stored as fp16 to halve L2 gather traffic (the SpMM stages
// are at the ~6300 B/cyc LTS cap; bytes are the only lever left).
// ---------------------------------------------------------------------------
__device__ __half g_buf0[TOT];                        // filtered  [N,128] fp16
__device__ __half g_buf1[TOT];                        // tmp       [N,128] fp16
__device__ int    g_cursor[3 * NNODES];               // per-row fill cursors == counts
__device__ int2   g_slots[3 * NNODES * SLOTS];        // (col, val-bits) buckets

// ---------------------------------------------------------------------------
// Zero the cursors (600 KB).
// ---------------------------------------------------------------------------
__global__ void zero_cursor_kernel() {
    int i = blockIdx.x * blockDim.x + threadIdx.x;
    if (i < 3 * NNODES) g_cursor[i] = 0;
}

// ---------------------------------------------------------------------------
// Fused bucket-scatter for all three matrices. blockIdx.y selects the matrix.
// 4 nnz per thread for ILP. theta (matrix 2) folds phi @ diag(theta) in.
// ---------------------------------------------------------------------------
__global__ void scatter_kernel(const int*   __restrict__ rows0, const float* __restrict__ vals0, int nnz0,
                               const int*   __restrict__ rows1, const float* __restrict__ vals1, int nnz1,
                               const int*   __restrict__ rows2, const float* __restrict__ vals2, int nnz2,
                               const float* __restrict__ theta) {
    const int m = blockIdx.y;
    const int* rows; const int* cols; const float* vals; int nnz;
    const float* th = nullptr;
    if (m == 0)      { rows = rows0; cols = rows0 + nnz0; vals = vals0; nnz = nnz0; }
    else if (m == 1) { rows = rows1; cols = rows1 + nnz1; vals = vals1; nnz = nnz1; }
    else             { rows = rows2; cols = rows2 + nnz2; vals = vals2; nnz = nnz2; th = theta; }

    int base = (blockIdx.x * blockDim.x + threadIdx.x) * 4;
    if (base >= nnz) return;

    int*  cur   = g_cursor + m * NNODES;
    int2* slots = g_slots + (unsigned)m * (unsigned)(NNODES * SLOTS);

    if (base + 4 <= nnz) {
        int4   r4 = *reinterpret_cast<const int4*>(rows + base);
        int4   c4 = *reinterpret_cast<const int4*>(cols + base);
        float4 v4 = *reinterpret_cast<const float4*>(vals + base);
        int   r[4] = {r4.x, r4.y, r4.z, r4.w};
        int   c[4] = {c4.x, c4.y, c4.z, c4.w};
        float v[4] = {v4.x, v4.y, v4.z, v4.w};
        #pragma unroll
        for (int k = 0; k < 4; k++) {
            float vv = v[k];
            if (th) vv *= __ldg(th + c[k]);
            int pos = atomicAdd(cur + r[k], 1);
            slots[(unsigned)r[k] * SLOTS + (unsigned)pos] = make_int2(c[k], __float_as_int(vv));
        }
    } else {
        for (int i = base; i < nnz && i < base + 4; i++) {
            int r = __ldg(rows + i);
            int c = __ldg(cols + i);
            float vv = __ldg(vals + i);
            if (th) vv *= __ldg(th + c);
            int pos = atomicAdd(cur + r, 1);
            slots[(unsigned)r * SLOTS + (unsigned)pos] = make_int2(c, __float_as_int(vv));
        }
    }
}

// ---------------------------------------------------------------------------
// Typed row-load / row-store helpers.
// fp32 rows: lane loads float4 (16 B) -> warp covers 512 B (4 lines).
// fp16 rows: lane loads uint2 (4 halves, 8 B) -> warp covers 256 B (2 lines).
// ---------------------------------------------------------------------------
__device__ __forceinline__ float4 load_row_f32(const float* base, unsigned c, int lane) {
    return __ldg(reinterpret_cast<const float4*>(base + c * FEAT) + lane);
}
__device__ __forceinline__ float4 load_row_f16(const __half* base, unsigned c, int lane) {
    uint2 raw = __ldg(reinterpret_cast<const uint2*>(base + c * FEAT) + lane);
    __half2 h0 = *reinterpret_cast<__half2*>(&raw.x);
    __half2 h1 = *reinterpret_cast<__half2*>(&raw.y);
    float2 f0 = __half22float2(h0);
    float2 f1 = __half22float2(h1);
    return make_float4(f0.x, f0.y, f1.x, f1.y);
}

// ---------------------------------------------------------------------------
// Gather SpMM: out[row,:] = sum_j val_j * dense[col_j, :]   (F = 128)
// One warp per row. Lane i prefetches entry i with one coalesced 8B load;
// cols/vals broadcast via shfl. 4 independent row loads in flight per batch
// (round-6 best config: no launch_bounds, ~40 regs, 61% occ).
// IN_HALF / OUT_HALF select fp16 storage; accumulation is always fp32.
// ---------------------------------------------------------------------------
template <bool IN_HALF, bool OUT_HALF, bool RELU>
__global__ void spmm_gather_kernel(int m,
                                   const void* __restrict__ dense_v,
                                   void*       __restrict__ out_v) {
    int row  = (blockIdx.x * blockDim.x + threadIdx.x) >> 5;
    int lane = threadIdx.x & 31;
    if (row >= NNODES) return;

    const float*  dense_f = (const float*) dense_v;
    const __half* dense_h = (const __half*)dense_v;

    int cnt = __ldg(g_cursor + m * NNODES + row);
    if (cnt > SLOTS) cnt = SLOTS;
    const int2* e = g_slots + (unsigned)m * (unsigned)(NNODES * SLOTS)
                           + (unsigned)row * SLOTS;

    // One coalesced load covers entries 0..31 for the whole warp.
    int2 my_e = make_int2(0, 0);
    if (lane < cnt) my_e = __ldg(e + lane);

    float4 acc0 = make_float4(0.f, 0.f, 0.f, 0.f);
    float4 acc1 = make_float4(0.f, 0.f, 0.f, 0.f);

    const int n32 = (cnt < 32) ? cnt : 32;
    int i = 0;
    for (; i + 4 <= n32; i += 4) {
        unsigned c0 = (unsigned)__shfl_sync(FULLM, my_e.x, i);
        unsigned c1 = (unsigned)__shfl_sync(FULLM, my_e.x, i + 1);
        unsigned c2 = (unsigned)__shfl_sync(FULLM, my_e.x, i + 2);
        unsigned c3 = (unsigned)__shfl_sync(FULLM, my_e.x, i + 3);
        float v0 = __int_as_float(__shfl_sync(FULLM, my_e.y, i));
        float v1 = __int_as_float(__shfl_sync(FULLM, my_e.y, i + 1));
        float v2 = __int_as_float(__shfl_sync(FULLM, my_e.y, i + 2));
        float v3 = __int_as_float(__shfl_sync(FULLM, my_e.y, i + 3));
        // 4 independent loads in flight
        float4 x0 = IN_HALF ? load_row_f16(dense_h, c0, lane) : load_row_f32(dense_f, c0, lane);
        float4 x1 = IN_HALF ? load_row_f16(dense_h, c1, lane) : load_row_f32(dense_f, c1, lane);
        float4 x2 = IN_HALF ? load_row_f16(dense_h, c2, lane) : load_row_f32(dense_f, c2, lane);
        float4 x3 = IN_HALF ? load_row_f16(dense_h, c3, lane) : load_row_f32(dense_f, c3, lane);
        acc0.x += v0 * x0.x; acc0.y += v0 * x0.y; acc0.z += v0 * x0.z; acc0.w += v0 * x0.w;
        acc1.x += v1 * x1.x; acc1.y += v1 * x1.y; acc1.z += v1 * x1.z; acc1.w += v1 * x1.w;
        acc0.x += v2 * x2.x; acc0.y += v2 * x2.y; acc0.z += v2 * x2.z; acc0.w += v2 * x2.w;
        acc1.x += v3 * x3.x; acc1.y += v3 * x3.y; acc1.z += v3 * x3.z; acc1.w += v3 * x3.w;
    }
    for (; i < n32; i++) {
        unsigned c0 = (unsigned)__shfl_sync(FULLM, my_e.x, i);
        float    v0 = __int_as_float(__shfl_sync(FULLM, my_e.y, i));
        float4 x0 = IN_HALF ? load_row_f16(dense_h, c0, lane) : load_row_f32(dense_f, c0, lane);
        acc0.x += v0 * x0.x; acc0.y += v0 * x0.y; acc0.z += v0 * x0.z; acc0.w += v0 * x0.w;
    }
    // Rare tail: rows with more than 32 entries (~1e-4 of rows).
    for (; i < cnt; i++) {
        int2 ee = __ldg(e + i);
        float vv = __int_as_float(ee.y);
        float4 x0 = IN_HALF ? load_row_f16(dense_h, (unsigned)ee.x, lane)
                            : load_row_f32(dense_f, (unsigned)ee.x, lane);
        acc0.x += vv * x0.x; acc0.y += vv * x0.y; acc0.z += vv * x0.z; acc0.w += vv * x0.w;
    }

    float4 r;
    r.x = acc0.x + acc1.x;
    r.y = acc0.y + acc1.y;
    r.z = acc0.z + acc1.z;
    r.w = acc0.w + acc1.w;
    if (RELU) {
        r.x = fmaxf(r.x, 0.f); r.y = fmaxf(r.y, 0.f);
        r.z = fmaxf(r.z, 0.f); r.w = fmaxf(r.w, 0.f);
    }

    if (OUT_HALF) {
        __half2 h0 = __floats2half2_rn(r.x, r.y);
        __half2 h1 = __floats2half2_rn(r.z, r.w);
        uint2 packed;
        packed.x = *reinterpret_cast<unsigned*>(&h0);
        packed.y = *reinterpret_cast<unsigned*>(&h1);
        reinterpret_cast<uint2*>((__half*)out_v + (unsigned)row * FEAT)[lane] = packed;
    } else {
        reinterpret_cast<float4*>((float*)out_v + (unsigned)row * FEAT)[lane] = r;
    }
}

// ---------------------------------------------------------------------------
// Launch sequence (graph-capturable).
// Inputs:
//   0 phi_indices int32[2,NNZ]  1 phi_values f32[NNZ]
//   2 phi_inv_indices           3 phi_inv_values
//   4 feature_indices           5 feature_values
//   6 weight_matrix f32[256,128] 7 theta f32[N]  8 dropout (ignored)
// ---------------------------------------------------------------------------
extern "C" void kernel_launch(void* const* d_in, const int* in_sizes, int n_in,
                              void* d_out, int out_size) {
    const int*   phi_idx    = (const int*)  d_in[0];
    const float* phi_vals   = (const float*)d_in[1];
    const int*   phinv_idx  = (const int*)  d_in[2];
    const float* phinv_vals = (const float*)d_in[3];
    const int*   feat_idx   = (const int*)  d_in[4];
    const float* feat_vals  = (const float*)d_in[5];
    const float* W          = (const float*)d_in[6];
    const float* theta      = (const float*)d_in[7];
    float*       out        = (float*)d_out;

    const int nnz_phi   = in_sizes[1];
    const int nnz_phinv = in_sizes[3];
    const int nnz_feat  = in_sizes[5];

    __half* buf0 = nullptr; __half* buf1 = nullptr;
    cudaGetSymbolAddress((void**)&buf0, g_buf0);
    cudaGetSymbolAddress((void**)&buf1, g_buf1);

    const int B = 256;

    // 1) zero per-row cursors
    zero_cursor_kernel<<<(3 * NNODES + B - 1) / B, B>>>();

    // 2) fused bucket scatter for all three matrices
    int nnz_max = nnz_feat;
    if (nnz_phinv > nnz_max) nnz_max = nnz_phinv;
    if (nnz_phi   > nnz_max) nnz_max = nnz_phi;
    dim3 sgrid((nnz_max + 4 * B - 1) / (4 * B), 3);
    scatter_kernel<<<sgrid, B>>>(feat_idx,  feat_vals,  nnz_feat,
                                 phinv_idx, phinv_vals, nnz_phinv,
                                 phi_idx,   phi_vals,   nnz_phi,
                                 theta);

    // 3) three gather SpMMs: f32 W -> f16 buf0 -> f16 buf1 -> f32 out (+ReLU)
    const int SG = (NNODES * 32 + B - 1) / B;    // warp per row
    spmm_gather_kernel<false, true,  false><<<SG, B>>>(0, W,    buf0);
    spmm_gather_kernel<true,  true,  false><<<SG, B>>>(1, buf0, buf1);
    spmm_gather_kernel<true,  false, true ><<<SG, B>>>(2, buf1, out);
}